// round 1
// baseline (speedup 1.0000x reference)
#include <cuda_runtime.h>
#include <math.h>

// BilateralSlice: out[b,c,i,j] = trilinear(grid[b,c, h(j), w(i), d(guide[b,i,j])])
//   h(j) = j * (Hg-1)/(W-1), w(i) = i * (Wg-1)/(H-1), d = guide * (Dg-1)
// Shapes (fixed by bench): grid (4,12,16,16,8) f32, guide (4,1,1024,1024) f32,
// input_image (4,3,1024,1024) f32 (unused), out (4,12,1024,1024) f32.

#define B_   4
#define CC   12
#define HG   16
#define WG   16
#define DG   8
#define HH   1024
#define WW_  1024

// SMEM layout (floats): idx = h*SH + w*SW + d*CC + c
// SW = DG*CC = 96; SH = WG*SW + 4 = 1540 (pad so h-stride != 0 mod 32 banks)
#define SW_F 96
#define SH_F 1540
#define SMEM_FLOATS (HG * SH_F)            // 24640
#define SMEM_BYTES  (SMEM_FLOATS * 4)      // 98560

__global__ void __launch_bounds__(256, 2)
bslice_kernel(const float* __restrict__ grid,
              const float* __restrict__ guide,
              float* __restrict__ out)
{
    extern __shared__ float s[];
    float4* s4 = (float4*)s;

    const int b  = blockIdx.y;
    const int i0 = blockIdx.x * 4;
    const int t  = threadIdx.x;

    // ---- Stage this batch's grid slab into SMEM, transposed to [h][w][d][c] ----
    // Global layout: grid[b][c][h][w][d], 2048 elems per channel, 24576 per batch.
    const float4* g4 = (const float4*)(grid + (size_t)b * (CC * HG * WG * DG));
    #pragma unroll
    for (int k = 0; k < 24; k++) {
        int idx = t + k * 256;          // float4 index, coalesced global read
        float4 v = g4[idx];
        int n = idx * 4;                // float index in global order
        int c = n >> 11;                // / (16*16*8)
        int r = n & 2047;
        int h = r >> 7;                 // / (16*8)
        int w = (r >> 3) & 15;
        int d = r & 7;                  // d, d+1, d+2, d+3 are the 4 comps
        int base = h * SH_F + w * SW_F + d * CC + c;
        s[base]      = v.x;
        s[base + 12] = v.y;
        s[base + 24] = v.z;
        s[base + 36] = v.w;
    }
    __syncthreads();

    // ---- Per-column (j) h-cell data: fixed across the 4 rows this thread does ----
    const int j0 = t * 4;
    int bh0[4], bh1[4];
    float fh[4];
    #pragma unroll
    for (int jj = 0; jj < 4; jj++) {
        float hhf = (float)(j0 + jj) * (15.0f / 1023.0f);
        int h0 = (int)hhf;            // hhf >= 0 so trunc == floor
        if (h0 > 15) h0 = 15;
        int h1 = h0 + 1; if (h1 > 15) h1 = 15;
        fh[jj]  = hhf - (float)h0;
        bh0[jj] = h0 * (SH_F / 4);    // float4 units (385)
        bh1[jj] = h1 * (SH_F / 4);
    }

    #pragma unroll
    for (int g = 0; g < 4; g++) {
        const int i = i0 + g;
        float wwf = (float)i * (15.0f / 1023.0f);
        int w0 = (int)wwf; if (w0 > 15) w0 = 15;
        int w1 = w0 + 1;   if (w1 > 15) w1 = 15;
        float fw = wwf - (float)w0;
        const int bw0 = w0 * (SW_F / 4);   // 24
        const int bw1 = w1 * (SW_F / 4);

        // guide for 4 consecutive pixels, vectorized + coalesced
        float4 gv = *(const float4*)(guide + ((size_t)b * HH + i) * WW_ + j0);
        float garr[4] = {gv.x, gv.y, gv.z, gv.w};

        float res[48];   // res[c*4 + jj]; all indices constant after unroll
        #pragma unroll
        for (int jj = 0; jj < 4; jj++) {
            float dc  = garr[jj] * 7.0f;
            float dfl = floorf(dc);
            dfl = fminf(fmaxf(dfl, 0.0f), 7.0f);
            int d0 = (int)dfl;
            int d1 = d0 + 1; if (d1 > 7) d1 = 7;
            float dw = dc - dfl;
            dw = fminf(fmaxf(dw, 0.0f), 1.0f);

            float accs[12];
            #pragma unroll
            for (int c = 0; c < 12; c++) accs[c] = 0.0f;

            const float whv[2]  = {1.0f - fh[jj], fh[jj]};
            const int   bhv[2]  = {bh0[jj], bh1[jj]};
            const float wwv[2]  = {1.0f - fw, fw};
            const int   bwv[2]  = {bw0, bw1};
            const float wdv[2]  = {1.0f - dw, dw};
            const int   bdv[2]  = {d0 * 3, d1 * 3};

            #pragma unroll
            for (int ch = 0; ch < 2; ch++)
            #pragma unroll
            for (int cw = 0; cw < 2; cw++)
            #pragma unroll
            for (int cd = 0; cd < 2; cd++) {
                float wgt = whv[ch] * wwv[cw] * wdv[cd];
                int a = bhv[ch] + bwv[cw] + bdv[cd];   // float4 index
                float4 q0 = s4[a];
                float4 q1 = s4[a + 1];
                float4 q2 = s4[a + 2];
                accs[0]  = fmaf(wgt, q0.x, accs[0]);
                accs[1]  = fmaf(wgt, q0.y, accs[1]);
                accs[2]  = fmaf(wgt, q0.z, accs[2]);
                accs[3]  = fmaf(wgt, q0.w, accs[3]);
                accs[4]  = fmaf(wgt, q1.x, accs[4]);
                accs[5]  = fmaf(wgt, q1.y, accs[5]);
                accs[6]  = fmaf(wgt, q1.z, accs[6]);
                accs[7]  = fmaf(wgt, q1.w, accs[7]);
                accs[8]  = fmaf(wgt, q2.x, accs[8]);
                accs[9]  = fmaf(wgt, q2.y, accs[9]);
                accs[10] = fmaf(wgt, q2.z, accs[10]);
                accs[11] = fmaf(wgt, q2.w, accs[11]);
            }
            #pragma unroll
            for (int c = 0; c < 12; c++) res[c * 4 + jj] = accs[c];
        }

        // ---- Coalesced float4 stores: 12 channels for this row ----
        #pragma unroll
        for (int c = 0; c < 12; c++) {
            float4 o = make_float4(res[c * 4 + 0], res[c * 4 + 1],
                                   res[c * 4 + 2], res[c * 4 + 3]);
            *(float4*)(out + (((size_t)b * CC + c) * HH + i) * WW_ + j0) = o;
        }
    }
}

extern "C" void kernel_launch(void* const* d_in, const int* in_sizes, int n_in,
                              void* d_out, int out_size)
{
    const float* grid  = (const float*)d_in[0];
    const float* guide = (const float*)d_in[1];
    // d_in[2] = input_image: only shapes matter, values unused by reference.
    float* out = (float*)d_out;

    cudaFuncSetAttribute(bslice_kernel,
                         cudaFuncAttributeMaxDynamicSharedMemorySize, SMEM_BYTES);
    dim3 gr(HH / 4, B_);
    bslice_kernel<<<gr, 256, SMEM_BYTES>>>(grid, guide, out);
}

// round 2
// speedup vs baseline: 1.7735x; 1.7735x over previous
#include <cuda_runtime.h>
#include <math.h>

// BilateralSlice: out[b,c,i,j] = trilinear(grid[b,c, h(j), w(i), d(guide[b,i,j])])
// Shapes: grid (4,12,16,16,8) f32, guide (4,1,1024,1024) f32, out (4,12,1024,1024) f32.
//
// R2 strategy: one CTA per image row. w0/w1/fw are constant per row, so the CTA
// first builds a w-interpolated slab Rw[h][d][c] (1536 floats, 6 KB smem); each
// pixel then reads only 4 corners (h0/h1 x d0/d1) = 192 B of LDS instead of 384 B.

#define CC   12
#define HG   16
#define WG   16
#define DG   8
#define HH   1024
#define WW_  1024

__global__ void __launch_bounds__(256, 2)
bslice_kernel(const float* __restrict__ grid,
              const float* __restrict__ guide,
              float* __restrict__ out)
{
    __shared__ float s[HG * DG * CC];      // [h][d][c]: idx = h*96 + d*12 + c
    float4* s4 = (float4*)s;               // float4 idx = h*24 + d*3 (+0,1,2)

    const int b = blockIdx.y;
    const int i = blockIdx.x;              // image row
    const int t = threadIdx.x;

    // ---- w cell for this row (constant across the row) ----
    const float wwf = (float)i * (15.0f / 1023.0f);
    int w0 = (int)wwf; if (w0 > 15) w0 = 15;
    int w1 = w0 + 1;   if (w1 > 15) w1 = 15;
    const float fw = wwf - (float)w0;

    // ---- Stage the w-interpolated slab: 384 float4-groups of (c,h,dq) ----
    // grid[b][c][h][w][d]; float4 over d (dq = d/4).
    const float4* g4 = (const float4*)grid;
    #pragma unroll
    for (int k = 0; k < 2; k++) {
        int idx = t + k * 256;
        if (idx < 384) {
            int c   = idx >> 5;            // 12 channels
            int rem = idx & 31;
            int h   = rem >> 1;            // 16 h
            int dq  = rem & 1;             // 2 quads of d
            int base = ((b * CC + c) * HG + h) * 32;   // float4 offset of [b,c,h,0,0]
            float4 a  = g4[base + w0 * 2 + dq];
            float4 bb = g4[base + w1 * 2 + dq];
            int so = h * 96 + dq * 48 + c; // d-major writes, c stride 1
            s[so]      = fmaf(fw, bb.x - a.x, a.x);
            s[so + 12] = fmaf(fw, bb.y - a.y, a.y);
            s[so + 24] = fmaf(fw, bb.z - a.z, a.z);
            s[so + 36] = fmaf(fw, bb.w - a.w, a.w);
        }
    }
    __syncthreads();

    // ---- Per-column h-cell data: thread owns 4 consecutive columns ----
    const int j0 = t * 4;
    float fh[4]; int bh0[4], bh1[4];
    #pragma unroll
    for (int jj = 0; jj < 4; jj++) {
        float hhf = (float)(j0 + jj) * (15.0f / 1023.0f);
        int h0 = (int)hhf; if (h0 > 15) h0 = 15;
        int h1 = h0 + 1;   if (h1 > 15) h1 = 15;
        fh[jj]  = hhf - (float)h0;
        bh0[jj] = h0 * 24;                 // float4 units
        bh1[jj] = h1 * 24;
    }

    // guide for 4 consecutive pixels (coalesced LDG.128)
    float4 gv = *(const float4*)(guide + ((size_t)b * HH + i) * WW_ + j0);
    float ga[4] = {gv.x, gv.y, gv.z, gv.w};

    float res[48];                          // res[c*4 + jj]
    #pragma unroll
    for (int jj = 0; jj < 4; jj++) {
        float dc  = ga[jj] * 7.0f;
        float dfl = floorf(dc);
        dfl = fminf(fmaxf(dfl, 0.0f), 7.0f);
        int d0 = (int)dfl;
        int d1 = d0 + 1; if (d1 > 7) d1 = 7;
        float dw = fminf(fmaxf(dc - dfl, 0.0f), 1.0f);
        const float fhj = fh[jj];

        const float wgt[4] = { (1.0f - fhj) * (1.0f - dw), (1.0f - fhj) * dw,
                               fhj * (1.0f - dw),           fhj * dw };
        const int   adr[4] = { bh0[jj] + d0 * 3, bh0[jj] + d1 * 3,
                               bh1[jj] + d0 * 3, bh1[jj] + d1 * 3 };

        float acc[12];
        #pragma unroll
        for (int c = 0; c < 12; c++) acc[c] = 0.0f;

        #pragma unroll
        for (int k = 0; k < 4; k++) {
            float wk = wgt[k];
            int a = adr[k];
            float4 q0 = s4[a];
            float4 q1 = s4[a + 1];
            float4 q2 = s4[a + 2];
            acc[0]  = fmaf(wk, q0.x, acc[0]);
            acc[1]  = fmaf(wk, q0.y, acc[1]);
            acc[2]  = fmaf(wk, q0.z, acc[2]);
            acc[3]  = fmaf(wk, q0.w, acc[3]);
            acc[4]  = fmaf(wk, q1.x, acc[4]);
            acc[5]  = fmaf(wk, q1.y, acc[5]);
            acc[6]  = fmaf(wk, q1.z, acc[6]);
            acc[7]  = fmaf(wk, q1.w, acc[7]);
            acc[8]  = fmaf(wk, q2.x, acc[8]);
            acc[9]  = fmaf(wk, q2.y, acc[9]);
            acc[10] = fmaf(wk, q2.z, acc[10]);
            acc[11] = fmaf(wk, q2.w, acc[11]);
        }
        #pragma unroll
        for (int c = 0; c < 12; c++) res[c * 4 + jj] = acc[c];
    }

    // ---- Coalesced float4 stores: 12 channels ----
    #pragma unroll
    for (int c = 0; c < 12; c++) {
        float4 o = make_float4(res[c * 4 + 0], res[c * 4 + 1],
                               res[c * 4 + 2], res[c * 4 + 3]);
        *(float4*)(out + (((size_t)b * CC + c) * HH + i) * WW_ + j0) = o;
    }
}

extern "C" void kernel_launch(void* const* d_in, const int* in_sizes, int n_in,
                              void* d_out, int out_size)
{
    const float* grid  = (const float*)d_in[0];
    const float* guide = (const float*)d_in[1];
    float* out = (float*)d_out;

    dim3 gr(HH, 4);                         // one CTA per (row, batch)
    bslice_kernel<<<gr, 256>>>(grid, guide, out);
}

// round 7
// speedup vs baseline: 2.0448x; 1.1530x over previous
#include <cuda_runtime.h>
#include <cuda_fp16.h>
#include <math.h>

// BilateralSlice: out[b,c,i,j] = trilinear(grid[b,c, h(j), w(i), d(guide[b,i,j])])
// Shapes: grid (4,12,16,16,8) f32, guide (4,1,1024,1024) f32, out (4,12,1024,1024) f32.
//
// R4 resubmit (R5 run was an infra failure): one CTA per image row; w-lerped
// slab stored in SMEM as fp16 ([h][d][c], d-stride 24B, h-stride 224B).
// Per pixel: 4 corners (h0/h1 x d0/d1) x 12 channels x 2B = 96 B of LDS
// (half of the fp32 version). Accumulation in fp32; only error source is one
// fp16 rounding of the slab values.

#define CC   12
#define HG   16
#define WG   16
#define DG   8
#define HH   1024
#define WW_  1024

#define DSTRIDE_H 12          // halves per d
#define HSTRIDE_H 112         // halves per h (96 + 16 pad)
#define DSTRIDE_B 24          // bytes
#define HSTRIDE_B 224         // bytes

__device__ __forceinline__ void corner_acc(const char* sb, int off, float w, float* acc)
{
    uint2 p0 = *(const uint2*)(sb + off);        // halves c0..c3
    uint2 p1 = *(const uint2*)(sb + off + 8);    // c4..c7
    uint2 p2 = *(const uint2*)(sb + off + 16);   // c8..c11
    float2 f;
    f = __half22float2(*(const __half2*)&p0.x); acc[0] = fmaf(w, f.x, acc[0]); acc[1] = fmaf(w, f.y, acc[1]);
    f = __half22float2(*(const __half2*)&p0.y); acc[2] = fmaf(w, f.x, acc[2]); acc[3] = fmaf(w, f.y, acc[3]);
    f = __half22float2(*(const __half2*)&p1.x); acc[4] = fmaf(w, f.x, acc[4]); acc[5] = fmaf(w, f.y, acc[5]);
    f = __half22float2(*(const __half2*)&p1.y); acc[6] = fmaf(w, f.x, acc[6]); acc[7] = fmaf(w, f.y, acc[7]);
    f = __half22float2(*(const __half2*)&p2.x); acc[8] = fmaf(w, f.x, acc[8]); acc[9] = fmaf(w, f.y, acc[9]);
    f = __half22float2(*(const __half2*)&p2.y); acc[10] = fmaf(w, f.x, acc[10]); acc[11] = fmaf(w, f.y, acc[11]);
}

__global__ void __launch_bounds__(256, 2)
bslice_kernel(const float* __restrict__ grid,
              const float* __restrict__ guide,
              float* __restrict__ out)
{
    __shared__ __half sh[HG * HSTRIDE_H];   // 1792 halves = 3584 B
    const char* sb = (const char*)sh;

    const int b = blockIdx.y;
    const int i = blockIdx.x;               // image row
    const int t = threadIdx.x;

    // ---- w cell for this row (constant across the row) ----
    const float wwf = (float)i * (15.0f / 1023.0f);
    int w0 = (int)wwf; if (w0 > 15) w0 = 15;
    int w1 = w0 + 1;   if (w1 > 15) w1 = 15;
    const float fw = wwf - (float)w0;

    // ---- Stage w-interpolated slab (fp32 lerp, fp16 store): 384 groups ----
    const float4* g4 = (const float4*)grid;
    #pragma unroll
    for (int k = 0; k < 2; k++) {
        int idx = t + k * 256;
        if (idx < 384) {                    // 12c * 16h * 2 d-quads
            int c   = idx >> 5;
            int rem = idx & 31;
            int h   = rem >> 1;
            int dq  = rem & 1;
            int base = ((b * CC + c) * HG + h) * 32;  // float4 offset of [b,c,h,0,0]
            float4 a  = g4[base + w0 * 2 + dq];
            float4 bb = g4[base + w1 * 2 + dq];
            int so = h * HSTRIDE_H + (dq * 4) * DSTRIDE_H + c;
            sh[so]                 = __float2half_rn(fmaf(fw, bb.x - a.x, a.x));
            sh[so + DSTRIDE_H]     = __float2half_rn(fmaf(fw, bb.y - a.y, a.y));
            sh[so + 2 * DSTRIDE_H] = __float2half_rn(fmaf(fw, bb.z - a.z, a.z));
            sh[so + 3 * DSTRIDE_H] = __float2half_rn(fmaf(fw, bb.w - a.w, a.w));
        }
    }
    __syncthreads();

    // ---- Per-column h cell: thread owns 4 consecutive columns ----
    const int j0 = t * 4;
    float fh[4]; int ho0[4], ho1[4];
    #pragma unroll
    for (int jj = 0; jj < 4; jj++) {
        float hhf = (float)(j0 + jj) * (15.0f / 1023.0f);
        int h0 = (int)hhf; if (h0 > 15) h0 = 15;
        int h1 = h0 + 1;   if (h1 > 15) h1 = 15;
        fh[jj]  = hhf - (float)h0;
        ho0[jj] = h0 * HSTRIDE_B;           // byte offsets
        ho1[jj] = h1 * HSTRIDE_B;
    }

    // guide for 4 consecutive pixels (coalesced LDG.128)
    float4 gv = *(const float4*)(guide + ((size_t)b * HH + i) * WW_ + j0);
    float ga[4] = {gv.x, gv.y, gv.z, gv.w};

    float res[48];                          // res[c*4 + jj]
    #pragma unroll
    for (int jj = 0; jj < 4; jj++) {
        float dc  = ga[jj] * 7.0f;
        float dfl = floorf(dc);
        dfl = fminf(fmaxf(dfl, 0.0f), 7.0f);
        int d0 = (int)dfl;
        int d1 = d0 + 1; if (d1 > 7) d1 = 7;
        float dw = fminf(fmaxf(dc - dfl, 0.0f), 1.0f);
        const float fhj = fh[jj];

        const float w00 = (1.0f - fhj) * (1.0f - dw);
        const float w01 = (1.0f - fhj) * dw;
        const float w10 = fhj * (1.0f - dw);
        const float w11 = fhj * dw;
        const int   o00 = ho0[jj] + d0 * DSTRIDE_B;
        const int   o01 = ho0[jj] + d1 * DSTRIDE_B;
        const int   o10 = ho1[jj] + d0 * DSTRIDE_B;
        const int   o11 = ho1[jj] + d1 * DSTRIDE_B;

        float acc[12];
        #pragma unroll
        for (int c = 0; c < 12; c++) acc[c] = 0.0f;

        corner_acc(sb, o00, w00, acc);
        corner_acc(sb, o01, w01, acc);
        corner_acc(sb, o10, w10, acc);
        corner_acc(sb, o11, w11, acc);

        #pragma unroll
        for (int c = 0; c < 12; c++) res[c * 4 + jj] = acc[c];
    }

    // ---- Coalesced float4 stores: 12 channels ----
    #pragma unroll
    for (int c = 0; c < 12; c++) {
        float4 o = make_float4(res[c * 4 + 0], res[c * 4 + 1],
                               res[c * 4 + 2], res[c * 4 + 3]);
        *(float4*)(out + (((size_t)b * CC + c) * HH + i) * WW_ + j0) = o;
    }
}

extern "C" void kernel_launch(void* const* d_in, const int* in_sizes, int n_in,
                              void* d_out, int out_size)
{
    const float* grid  = (const float*)d_in[0];
    const float* guide = (const float*)d_in[1];
    float* out = (float*)d_out;

    dim3 gr(HH, 4);                         // one CTA per (row, batch)
    bslice_kernel<<<gr, 256>>>(grid, guide, out);
}

// round 9
// speedup vs baseline: 2.3520x; 1.1502x over previous
#include <cuda_runtime.h>
#include <cuda_fp16.h>
#include <math.h>

// BilateralSlice: out[b,c,i,j] = trilinear(grid[b,c, h(j), w(i), d(guide[b,i,j])])
// Shapes: grid (4,12,16,16,8) f32, guide (4,1,1024,1024) f32, out (4,12,1024,1024) f32.
//
// R8: two CTAs per image row (512 cols each, 2 cols/thread) to cut register
// pressure (res[24] vs res[48]) and double occupancy. A half-row touches only
// h-slices [hbase, hbase+8] (hbase = half*7), so the fp16 w-lerped slab is
// 9 x 112 halves = 2 KB and stages in one pass (216 groups).

#define CC   12
#define HG   16
#define DG   8
#define HH   1024
#define WW_  1024

#define DSTRIDE_H 12          // halves per d
#define HSTRIDE_H 112         // halves per h (96 + 16 pad)
#define DSTRIDE_B 24          // bytes
#define HSTRIDE_B 224         // bytes
#define NSLICE    9           // h-slices per half-row

__device__ __forceinline__ void corner_acc(const char* sb, int off, float w, float* acc)
{
    uint2 p0 = *(const uint2*)(sb + off);        // halves c0..c3
    uint2 p1 = *(const uint2*)(sb + off + 8);    // c4..c7
    uint2 p2 = *(const uint2*)(sb + off + 16);   // c8..c11
    float2 f;
    f = __half22float2(*(const __half2*)&p0.x); acc[0] = fmaf(w, f.x, acc[0]); acc[1] = fmaf(w, f.y, acc[1]);
    f = __half22float2(*(const __half2*)&p0.y); acc[2] = fmaf(w, f.x, acc[2]); acc[3] = fmaf(w, f.y, acc[3]);
    f = __half22float2(*(const __half2*)&p1.x); acc[4] = fmaf(w, f.x, acc[4]); acc[5] = fmaf(w, f.y, acc[5]);
    f = __half22float2(*(const __half2*)&p1.y); acc[6] = fmaf(w, f.x, acc[6]); acc[7] = fmaf(w, f.y, acc[7]);
    f = __half22float2(*(const __half2*)&p2.x); acc[8] = fmaf(w, f.x, acc[8]); acc[9] = fmaf(w, f.y, acc[9]);
    f = __half22float2(*(const __half2*)&p2.y); acc[10] = fmaf(w, f.x, acc[10]); acc[11] = fmaf(w, f.y, acc[11]);
}

__global__ void __launch_bounds__(256, 4)
bslice_kernel(const float* __restrict__ grid,
              const float* __restrict__ guide,
              float* __restrict__ out)
{
    __shared__ __half sh[NSLICE * HSTRIDE_H];   // 1008 halves = 2016 B
    const char* sb = (const char*)sh;

    const int half = blockIdx.x & 1;
    const int i    = blockIdx.x >> 1;       // image row
    const int b    = blockIdx.y;
    const int t    = threadIdx.x;
    const int hbase = half * 7;             // h-slices [hbase, hbase+8]

    // ---- w cell for this row (constant across the row) ----
    const float wwf = (float)i * (15.0f / 1023.0f);
    int w0 = (int)wwf; if (w0 > 15) w0 = 15;
    int w1 = w0 + 1;   if (w1 > 15) w1 = 15;
    const float fw = wwf - (float)w0;

    // ---- Stage w-interpolated slab (fp32 lerp, fp16 store): 216 groups ----
    const float4* g4 = (const float4*)grid;
    if (t < 216) {                          // 12c * 9h * 2 d-quads
        int c   = t / 18;
        int rem = t - c * 18;
        int h   = rem >> 1;
        int dq  = rem & 1;
        int base = ((b * CC + c) * HG + (hbase + h)) * 32;  // float4 off of [b,c,hg,0,0]
        float4 a  = g4[base + w0 * 2 + dq];
        float4 bb = g4[base + w1 * 2 + dq];
        int so = h * HSTRIDE_H + (dq * 4) * DSTRIDE_H + c;
        sh[so]                 = __float2half_rn(fmaf(fw, bb.x - a.x, a.x));
        sh[so + DSTRIDE_H]     = __float2half_rn(fmaf(fw, bb.y - a.y, a.y));
        sh[so + 2 * DSTRIDE_H] = __float2half_rn(fmaf(fw, bb.z - a.z, a.z));
        sh[so + 3 * DSTRIDE_H] = __float2half_rn(fmaf(fw, bb.w - a.w, a.w));
    }
    __syncthreads();

    // ---- Thread owns 2 consecutive columns ----
    const int j0 = half * 512 + t * 2;

    float2 gv = *(const float2*)(guide + ((size_t)b * HH + i) * WW_ + j0);
    float ga[2] = {gv.x, gv.y};

    float res[24];                          // res[c*2 + jj]
    #pragma unroll
    for (int jj = 0; jj < 2; jj++) {
        float hhf = (float)(j0 + jj) * (15.0f / 1023.0f);
        int h0 = (int)hhf; if (h0 > 15) h0 = 15;
        int h1 = h0 + 1;   if (h1 > 15) h1 = 15;
        const float fhj = hhf - (float)h0;
        const int ho0 = (h0 - hbase) * HSTRIDE_B;
        const int ho1 = (h1 - hbase) * HSTRIDE_B;

        float dc  = ga[jj] * 7.0f;
        float dfl = floorf(dc);
        dfl = fminf(fmaxf(dfl, 0.0f), 7.0f);
        int d0 = (int)dfl;
        int d1 = d0 + 1; if (d1 > 7) d1 = 7;
        float dw = fminf(fmaxf(dc - dfl, 0.0f), 1.0f);

        const float w00 = (1.0f - fhj) * (1.0f - dw);
        const float w01 = (1.0f - fhj) * dw;
        const float w10 = fhj * (1.0f - dw);
        const float w11 = fhj * dw;

        float acc[12];
        #pragma unroll
        for (int c = 0; c < 12; c++) acc[c] = 0.0f;

        corner_acc(sb, ho0 + d0 * DSTRIDE_B, w00, acc);
        corner_acc(sb, ho0 + d1 * DSTRIDE_B, w01, acc);
        corner_acc(sb, ho1 + d0 * DSTRIDE_B, w10, acc);
        corner_acc(sb, ho1 + d1 * DSTRIDE_B, w11, acc);

        #pragma unroll
        for (int c = 0; c < 12; c++) res[c * 2 + jj] = acc[c];
    }

    // ---- Coalesced float2 stores: 12 channels ----
    #pragma unroll
    for (int c = 0; c < 12; c++) {
        float2 o = make_float2(res[c * 2 + 0], res[c * 2 + 1]);
        *(float2*)(out + (((size_t)b * CC + c) * HH + i) * WW_ + j0) = o;
    }
}

extern "C" void kernel_launch(void* const* d_in, const int* in_sizes, int n_in,
                              void* d_out, int out_size)
{
    const float* grid  = (const float*)d_in[0];
    const float* guide = (const float*)d_in[1];
    float* out = (float*)d_out;

    dim3 gr(HH * 2, 4);                     // two CTAs per (row, batch)
    bslice_kernel<<<gr, 256>>>(grid, guide, out);
}